// round 17
// baseline (speedup 1.0000x reference)
#include <cuda_runtime.h>
#include <cuda_fp16.h>

// Problem geometry (fixed by reference)
#define NCH    2560      // readout channels
#define NT     256       // ticks
#define NCELLS 40000     // cells per face
#define CAP    320       // max entries per output channel (Poisson(~100) safe)

// ---- static device scratch (no allocation allowed) ----
__device__ int     g_counts[NCH];           // zero-init; main re-zeroes
__device__ ushort2 g_entries[NCH * CAP];    // per-channel partner pairs
__device__ __align__(16) __half g_xh[NCH * NT];  // relu(x) in fp16, 1.3 MB
__device__ float   g_wf[8];                 // folded: w00,w10,w20,w01,w11,w21,be0,be1

typedef unsigned long long u64;

// Packed f32x2 FMA (sm_100+): d = a*b+c on both 32-bit halves. SASS: FFMA2.
__device__ __forceinline__ u64 fma2(u64 a, u64 b, u64 c) {
    u64 d;
    asm("fma.rn.f32x2 %0, %1, %2, %3;" : "=l"(d) : "l"(a), "l"(b), "l"(c));
    return d;
}
__device__ __forceinline__ float lo32(u64 v) { return __uint_as_float((unsigned)v); }
__device__ __forceinline__ float hi32(u64 v) { return __uint_as_float((unsigned)(v >> 32)); }
__device__ __forceinline__ u64 pack2(float a, float b) {
    return (u64)__float_as_uint(a) | ((u64)__float_as_uint(b) << 32);
}
// half2 word -> packed f32x2
__device__ __forceinline__ u64 h2f2(unsigned hw) {
    __half2 h = *reinterpret_cast<__half2*>(&hw);
    float2 f = __half22float2(h);
    return pack2(f.x, f.y);
}

// Read logical element i from an index table that may be int32 or int64
// (little-endian: lo word first; all values nonnegative < 2^31).
__device__ __forceinline__ int idx_ld(const int* p, int i, bool is64) {
    return is64 ? p[2 * i] : p[i];
}

#define PREP_BLOCKS  640                    // 640*256 threads, one float4 each = NCH*NT/4
#define BUILD_BLOCKS 313                    // ceil(80000/256)

// Fused pre-kernel: relu -> out plane0 (fp32) + g_xh (fp16) (blocks [0,PREP)),
// bucket build (blocks [PREP, PREP+BUILD)), weight fold (last block).
// g_counts is zero (module init on run 1; main_kernel resets it every run).
__global__ void pre_kernel(const float* __restrict__ x, float* __restrict__ out,
                           const float* __restrict__ W1, const float* __restrict__ b1,
                           const float* __restrict__ W2, const float* __restrict__ b2,
                           const int* __restrict__ gi0, const int* __restrict__ gi1,
                           const int* __restrict__ wc00, const int* __restrict__ wc01,
                           const int* __restrict__ wc02, const int* __restrict__ wc10,
                           const int* __restrict__ wc11, const int* __restrict__ wc12) {
    int b = blockIdx.x, tid = threadIdx.x;
    if (b < PREP_BLOCKS) {
        int i = b * 256 + tid;                      // float4 index, < 163840
        float4 v = ((const float4*)x)[i];
        v.x = fmaxf(v.x, 0.f); v.y = fmaxf(v.y, 0.f);
        v.z = fmaxf(v.z, 0.f); v.w = fmaxf(v.w, 0.f);
        ((float4*)out)[i] = v;                      // plane 0 = relu(x), fp32 exact
        __half2 h01 = __floats2half2_rn(v.x, v.y);
        __half2 h23 = __floats2half2_rn(v.z, v.w);
        uint2 hv;
        hv.x = *reinterpret_cast<unsigned*>(&h01);
        hv.y = *reinterpret_cast<unsigned*>(&h23);
        ((uint2*)g_xh)[i] = hv;                     // fp16 gather source
        return;
    }
    if (b < PREP_BLOCKS + BUILD_BLOCKS) {
        int gid = (b - PREP_BLOCKS) * 256 + tid;
        if (gid >= 2 * NCELLS) return;
        // dtype sniff: int64 => these words are hi-halves (all 0). For int32
        // they are three distinct permutation channels (at most one can be 0).
        bool is64 = (wc00[1] == 0 && wc00[3] == 0 && wc00[5] == 0);
        int f = gid / NCELLS;
        int n = gid - f * NCELLS;
        const int* gi = f ? gi1 : gi0;
        const int* wa = f ? wc10 : wc00;
        const int* wb = f ? wc11 : wc01;
        const int* wd = f ? wc12 : wc02;

        int w0 = idx_ld(gi, n * 3 + 0, is64);
        int w1 = idx_ld(gi, n * 3 + 1, is64);
        int w2 = idx_ld(gi, n * 3 + 2, is64);
        int c0 = idx_ld(wa, w0 * 2 + 1, is64);      // plane 0, in [0,800)
        int c1 = idx_ld(wb, w1 * 2 + 1, is64);      // plane 1, in [800,1600)
        int c2 = idx_ld(wd, w2 * 2 + 1, is64);      // plane 2, in [1600,2560)

        // Bucket c stores the OTHER two channels (slot implied by c's range).
        int s0 = atomicAdd(&g_counts[c0], 1);
        if (s0 < CAP) g_entries[c0 * CAP + s0] =
            make_ushort2((unsigned short)c1, (unsigned short)c2);
        int s1 = atomicAdd(&g_counts[c1], 1);
        if (s1 < CAP) g_entries[c1 * CAP + s1] =
            make_ushort2((unsigned short)c0, (unsigned short)c2);
        int s2 = atomicAdd(&g_counts[c2], 1);
        if (s2 < CAP) g_entries[c2 * CAP + s2] =
            make_ushort2((unsigned short)c0, (unsigned short)c1);
        return;
    }
    // fold block: W1(3x8)@W2(8x2), beff = b1@W2 + b2
    if (tid == 0) {
        float s0 = b2[0], s1 = b2[1];
        float a[6] = {0.f, 0.f, 0.f, 0.f, 0.f, 0.f};
        #pragma unroll
        for (int h = 0; h < 8; ++h) {
            float v0 = W2[h * 2 + 0], v1 = W2[h * 2 + 1];
            s0 = fmaf(b1[h], v0, s0);
            s1 = fmaf(b1[h], v1, s1);
            #pragma unroll
            for (int r = 0; r < 3; ++r) {
                a[r]     = fmaf(W1[r * 8 + h], v0, a[r]);
                a[r + 3] = fmaf(W1[r * 8 + h], v1, a[r + 3]);
            }
        }
        #pragma unroll
        for (int r = 0; r < 6; ++r) g_wf[r] = a[r];
        g_wf[6] = s0; g_wf[7] = s1;
    }
}

// Main: ONE WARP per channel (1280 blocks x 64 threads = 2 warps/block).
// fp16 partner rows: 512B/row = 32 lanes x LDG.128 (8 ticks per lane).
// Self row + bias stay fp32-exact (loaded from out plane 0).
// Per entry per lane: 2x LDG.128 + 8 h2->f2 cvt + 16 FFMA2 + 16 FMNMX.
__global__ __launch_bounds__(64) void main_kernel(float* __restrict__ out) {
    int w    = threadIdx.x >> 5;                    // warp in block (0/1)
    int lane = threadIdx.x & 31;
    int c    = blockIdx.x * 2 + w;                  // this warp's channel

    int slot = (c >= 800) + (c >= 1600);            // plane of channel c
    float ws0 = g_wf[slot],              ws1 = g_wf[3 + slot];
    float wa0 = g_wf[slot == 0 ? 1 : 0], wa1 = g_wf[slot == 0 ? 4 : 3];
    float wb0 = g_wf[slot == 2 ? 1 : 2], wb1 = g_wf[slot == 2 ? 4 : 5];
    float be0 = g_wf[6], be1 = g_wf[7];
    u64 wa0p = pack2(wa0, wa0), wb0p = pack2(wb0, wb0);
    u64 wa1p = pack2(wa1, wa1), wb1p = pack2(wb1, wb1);

    // Self row (fp32 exact): ticks [8*lane, 8*lane+8) = 2 float4.
    const float4* p0 = (const float4*)out;          // plane 0
    float4 sA = p0[c * 64 + 2 * lane];
    float4 sB = p0[c * 64 + 2 * lane + 1];
    u64 b0[4], b1[4];
    b0[0] = pack2(fmaf(sA.x, ws0, be0), fmaf(sA.y, ws0, be0));
    b0[1] = pack2(fmaf(sA.z, ws0, be0), fmaf(sA.w, ws0, be0));
    b0[2] = pack2(fmaf(sB.x, ws0, be0), fmaf(sB.y, ws0, be0));
    b0[3] = pack2(fmaf(sB.z, ws0, be0), fmaf(sB.w, ws0, be0));
    b1[0] = pack2(fmaf(sA.x, ws1, be1), fmaf(sA.y, ws1, be1));
    b1[1] = pack2(fmaf(sA.z, ws1, be1), fmaf(sA.w, ws1, be1));
    b1[2] = pack2(fmaf(sB.x, ws1, be1), fmaf(sB.y, ws1, be1));
    b1[3] = pack2(fmaf(sB.z, ws1, be1), fmaf(sB.w, ws1, be1));

    __shared__ ushort2 sE[2][CAP];
    int cnt = min(g_counts[c], CAP);
    for (int i = lane; i < cnt; i += 32) sE[w][i] = g_entries[c * CAP + i];
    __syncwarp();
    if (lane == 0) g_counts[c] = 0;                 // reset for next replay

    const uint4* xh = (const uint4*)g_xh;           // fp16 rows, 32 x 16B chunks
    float m0[8], m1[8];
    #pragma unroll
    for (int k = 0; k < 8; ++k) { m0[k] = 0.f; m1[k] = 0.f; }

    #pragma unroll 2
    for (int i = 0; i < cnt; ++i) {
        ushort2 e = sE[w][i];
        uint4 A = xh[(int)e.x * 32 + lane];
        uint4 B = xh[(int)e.y * 32 + lane];
        #define STEP(j, Aw, Bw)                                                \
        {                                                                      \
            u64 av = h2f2(Aw), bv = h2f2(Bw);                                  \
            u64 t0 = fma2(bv, wb0p, fma2(av, wa0p, b0[j]));                    \
            m0[2*(j)]   = fmaxf(m0[2*(j)],   lo32(t0));                        \
            m0[2*(j)+1] = fmaxf(m0[2*(j)+1], hi32(t0));                        \
            u64 t1 = fma2(bv, wb1p, fma2(av, wa1p, b1[j]));                    \
            m1[2*(j)]   = fmaxf(m1[2*(j)],   lo32(t1));                        \
            m1[2*(j)+1] = fmaxf(m1[2*(j)+1], hi32(t1));                        \
        }
        STEP(0, A.x, B.x);
        STEP(1, A.y, B.y);
        STEP(2, A.z, B.z);
        STEP(3, A.w, B.w);
        #undef STEP
    }

    // out layout (1, 3, NCH, NT): plane 0 written by pre_kernel.
    float4* o4 = (float4*)out;
    int i1 = NCH * 64 + c * 64 + 2 * lane;
    int i2 = 2 * NCH * 64 + c * 64 + 2 * lane;
    o4[i1]     = make_float4(m0[0], m0[1], m0[2], m0[3]);
    o4[i1 + 1] = make_float4(m0[4], m0[5], m0[6], m0[7]);
    o4[i2]     = make_float4(m1[0], m1[1], m1[2], m1[3]);
    o4[i2 + 1] = make_float4(m1[4], m1[5], m1[6], m1[7]);
}

extern "C" void kernel_launch(void* const* d_in, const int* in_sizes, int n_in,
                              void* d_out, int out_size) {
    const float* x  = (const float*)d_in[0];
    const float* W1 = (const float*)d_in[1];
    const float* b1 = (const float*)d_in[2];
    const float* W2 = (const float*)d_in[3];
    const float* b2 = (const float*)d_in[4];
    const int* gi0  = (const int*)d_in[5];
    const int* gi1  = (const int*)d_in[6];
    const int* wc00 = (const int*)d_in[7];
    const int* wc01 = (const int*)d_in[8];
    const int* wc02 = (const int*)d_in[9];
    const int* wc10 = (const int*)d_in[10];
    const int* wc11 = (const int*)d_in[11];
    const int* wc12 = (const int*)d_in[12];

    pre_kernel<<<PREP_BLOCKS + BUILD_BLOCKS + 1, 256>>>(
        x, (float*)d_out, W1, b1, W2, b2,
        gi0, gi1, wc00, wc01, wc02, wc10, wc11, wc12);
    main_kernel<<<NCH / 2, 64>>>((float*)d_out);
}